// round 15
// baseline (speedup 1.0000x reference)
#include <cuda_runtime.h>

#define NIN     64
#define NOUT    64
#define NJ      (NIN * NOUT)       // 4096
#define NKNOTS  10
#define NBASIS  6
#define BATCH_TILE 14
#define THREADS 512

// ---- dynamic shared layout (bytes) ----
#define SFEAT_OFF   0
#define SFEAT_BYTES (7 * BATCH_TILE * NIN * 4)      // 25088 [c][bl][i]
#define SYPART_OFF  (SFEAT_OFF + SFEAT_BYTES)
#define SYPART_BYTES (BATCH_TILE * 16 * 32 * 16)    // 114688 [bl][oq][lane]
#define SPART_OFF   (SYPART_OFF + SYPART_BYTES)
#define SPART_BYTES (BATCH_TILE * 16 * 2 * 16)      // 7168
#define SMEM_TOTAL  (SPART_OFF + SPART_BYTES)       // 146944

typedef unsigned long long ull;
__device__ __forceinline__ ull pack2(float lo, float hi) {
    ull r; asm("mov.b64 %0, {%1, %2};" : "=l"(r) : "f"(lo), "f"(hi)); return r;
}
#define FMA2(d,a,b,c) asm("fma.rn.f32x2 %0, %1, %2, %3;" : "=l"(d) : "l"(a), "l"(b), "l"(c))
#define MUL2(d,a,b)   asm("mul.rn.f32x2 %0, %1, %2;"     : "=l"(d) : "l"(a), "l"(b))
#define ADD2(d,a,b)   asm("add.rn.f32x2 %0, %1, %2;"     : "=l"(d) : "l"(a), "l"(b))
#define UNPK(lo,hi,p) asm("mov.b64 {%0, %1}, %2;" : "=f"(lo), "=f"(hi) : "l"(p))
#define ABSMASK 0x7FFFFFFF7FFFFFFFULL
#define SIGN2   0x8000000080000000ULL
#define NEG1X2  0xBF800000BF800000ULL

// L2-resident accumulator + ticket. Zero at module load; last block resets
// each launch (graph-replay safe).
__device__ __align__(16) float g_splacc[NJ];
__device__ unsigned int g_ticket;

struct Smem {
    float  (*sfeat)[BATCH_TILE][NIN];   // [c][bl][i]
    float4 (*sypart)[16][32];           // [bl][oq][lane]
    float4 (*spart)[2];                 // [item][half]
};

template <bool FULL>
__device__ __forceinline__
void phase2(const Smem& S, int nbl, int lane, int oq,
            const ull cb01[4][NBASIS], const ull csp01[4],
            const ull crs01[4], ull acc01[4])
{
    #pragma unroll
    for (int bl = 0; bl < BATCH_TILE; bl++) {
        if (!FULL && bl >= nbl) break;
        ull f01[7];
        #pragma unroll
        for (int c = 0; c < 7; c++)
            f01[c] = *(const ull*)&S.sfeat[c][bl][lane * 2];

        float4 yp;
        float* ypp = (float*)&yp;
        #pragma unroll
        for (int q = 0; q < 4; q++) {
            ull s01;
            MUL2(s01, cb01[q][0], f01[0]);
            #pragma unroll
            for (int c = 1; c < NBASIS; c++)
                FMA2(s01, cb01[q][c], f01[c], s01);
            ull a01 = s01 & ABSMASK;             // packed |.|
            ADD2(acc01[q], acc01[q], a01);
            ull t01;
            MUL2(t01, csp01[q], s01);
            FMA2(t01, crs01[q], f01[6], t01);
            float t0, t1; UNPK(t0, t1, t01);
            ypp[q] = t0 + t1;
        }
        S.sypart[bl][oq][lane] = yp;    // fire-and-forget
    }
}

__global__ __launch_bounds__(THREADS, 1)
void kan_fused_kernel(const float* __restrict__ x,
                      const float* __restrict__ c_basis,
                      const float* __restrict__ c_spl,
                      const float* __restrict__ c_res,
                      const float* __restrict__ grid,
                      float* __restrict__ y_out,
                      float* __restrict__ reg_out,
                      int batch, float inv_batch, int nblocks)
{
    extern __shared__ __align__(16) char smem_raw[];
    Smem S;
    S.sfeat  = (float  (*)[BATCH_TILE][NIN])(smem_raw + SFEAT_OFF);
    S.sypart = (float4 (*)[16][32])(smem_raw + SYPART_OFF);
    S.spart  = (float4 (*)[2])(smem_raw + SPART_OFF);
    __shared__ int s_last;

    const int t    = threadIdx.x;
    const int lane = t & 31;
    const int oq   = t >> 5;
    const int b0   = blockIdx.x * BATCH_TILE;
    const int nbl  = min(BATCH_TILE, batch - b0);

    // ---- coefficients: LDGs issued first; latency hides under phase 1 ----
    ull cb01[4][NBASIS], csp01[4], crs01[4];
    #pragma unroll
    for (int q = 0; q < 4; q++) {
        int j0 = (oq * 4 + q) * NIN + lane * 2;
        const float4* p4 = (const float4*)(c_basis + (size_t)j0 * NBASIS);
        float4 f0 = __ldg(&p4[0]);
        float4 f1 = __ldg(&p4[1]);
        float4 f2 = __ldg(&p4[2]);
        cb01[q][0] = pack2(f0.x, f1.z);
        cb01[q][1] = pack2(f0.y, f1.w);
        cb01[q][2] = pack2(f0.z, f2.x);
        cb01[q][3] = pack2(f0.w, f2.y);
        cb01[q][4] = pack2(f1.x, f2.z);
        cb01[q][5] = pack2(f1.y, f2.w);
        csp01[q] = *(const ull*)&c_spl[j0];
        crs01[q] = *(const ull*)&c_res[j0];
    }

    // ---- phase 1: uniform-knot basis + silu, pure register math, no LDS ----
    // grid rows are uniform: kn[m] = kn0 + m*h. With u = (x-kn0)/h:
    //   (x-kn[m])/(kn[m+K]-kn[m])        = (u-m)/K
    //   (kn[m+K+1]-x)/(kn[m+K+1]-kn[m+1]) = (m+K+1-u)/K
    //   indicator(kn[m] <= x < kn[m+1])   = (m <= u < m+1)
    if (t < BATCH_TILE * 32) {
        const int ip = t & 31;
        const int bl = t >> 5;
        int b = b0 + bl;
        float2 xv = (b < batch) ? *(const float2*)&x[(size_t)b * NIN + ip * 2]
                                : make_float2(0.f, 0.f);
        int i0 = ip * 2;
        float kn0a = __ldg(&grid[(size_t)i0 * NKNOTS]);
        float kn1a = __ldg(&grid[(size_t)i0 * NKNOTS + 1]);
        float kn0b = __ldg(&grid[(size_t)(i0 + 1) * NKNOTS]);
        float kn1b = __ldg(&grid[(size_t)(i0 + 1) * NKNOTS + 1]);
        float ua = (xv.x - kn0a) / (kn1a - kn0a);
        float ub = (xv.y - kn0b) / (kn1b - kn0b);
        ull u01 = pack2(ua, ub);

        // pum[m] = u - m  (packed)
        ull pum[NKNOTS];
        #pragma unroll
        for (int m = 0; m < NKNOTS; m++) {
            float fm = -(float)m;
            ull cm = pack2(fm, fm);
            ADD2(pum[m], u01, cm);
        }

        // bases init: bs[m] = ge[m] - ge[m+1], ge[m] = (pum[m] >= 0)
        ull bs01[9];
        {
            const ull neg1 = NEG1X2;
            float dA, dB; UNPK(dA, dB, pum[0]);
            ull gprev = pack2(dA >= 0.f ? 1.f : 0.f, dB >= 0.f ? 1.f : 0.f);
            #pragma unroll
            for (int m = 0; m < 9; m++) {
                UNPK(dA, dB, pum[m + 1]);
                ull gnext = pack2(dA >= 0.f ? 1.f : 0.f, dB >= 0.f ? 1.f : 0.f);
                FMA2(bs01[m], gnext, neg1, gprev);
                gprev = gnext;
            }
        }

        // recursion: bs[m] = ((u-m)*bs[m] + (m+K+1-u)*bs[m+1]) / K
        #pragma unroll
        for (int K = 1; K <= 3; K++) {
            const float invK = (K == 2) ? 0.5f : (K == 3) ? (1.0f / 3.0f) : 1.0f;
            const ull invK2 = pack2(invK, invK);
            #pragma unroll
            for (int m = 0; m <= 8 - K; m++) {
                ull w = pum[m + K + 1] ^ SIGN2;      // (m+K+1) - u
                ull tt, nb;
                MUL2(tt, w, bs01[m + 1]);
                FMA2(nb, pum[m], bs01[m], tt);
                if (K > 1) { MUL2(nb, nb, invK2); }
                bs01[m] = nb;
            }
        }
        #pragma unroll
        for (int c = 0; c < NBASIS; c++)
            *(ull*)&S.sfeat[c][bl][ip * 2] = bs01[c];
        float sA = xv.x / (1.0f + __expf(-xv.x));
        float sB = xv.y / (1.0f + __expf(-xv.y));
        *(ull*)&S.sfeat[6][bl][ip * 2] = pack2(sA, sB);
    }
    __syncthreads();

    // ---- phase 2: packed-FMA spl / y-partial / packed |spl| ----
    ull acc01[4] = {0ull, 0ull, 0ull, 0ull};
    if (nbl == BATCH_TILE) phase2<true >(S, nbl, lane, oq, cb01, csp01, crs01, acc01);
    else                   phase2<false>(S, nbl, lane, oq, cb01, csp01, crs01, acc01);

    // ---- issue atomics NOW so L2 drain overlaps the epilogue ----
    #pragma unroll
    for (int q = 0; q < 4; q++) {
        float a0, a1; UNPK(a0, a1, acc01[q]);
        int j = (oq * 4 + q) * NIN + lane * 2;
        atomicAdd(&g_splacc[j],     a0);
        atomicAdd(&g_splacc[j + 1], a1);
    }
    __syncthreads();

    // ---- epilogue: reduce lane dim (2 threads per output float4) ----
    {
        int item = t >> 1, half = t & 1;
        int bl = item >> 4, oqr = item & 15;
        if (t < BATCH_TILE * 16 * 2 && bl < nbl) {
            float4 s = make_float4(0.f, 0.f, 0.f, 0.f);
            int base = half * 16;
            #pragma unroll
            for (int k = 0; k < 16; k++) {
                int ls = base + ((k + (t & 15)) & 15);
                float4 v = S.sypart[bl][oqr][ls];
                s.x += v.x; s.y += v.y; s.z += v.z; s.w += v.w;
            }
            S.spart[item][half] = s;
        }
    }
    __syncthreads();
    {
        int item = t;
        int bl = item >> 4, oqr = item & 15;
        if (item < BATCH_TILE * 16 && bl < nbl) {
            float4 a = S.spart[item][0];
            float4 b = S.spart[item][1];
            const float sc = 1.0f / NIN;
            a.x = (a.x + b.x) * sc; a.y = (a.y + b.y) * sc;
            a.z = (a.z + b.z) * sc; a.w = (a.w + b.w) * sc;
            *(float4*)&y_out[(size_t)(b0 + bl) * NOUT + oqr * 4] = a;
        }
    }

    // ---- last-block-done: finalize spl_reg (inline norm, tail-only) ----
    __threadfence();
    __syncthreads();
    if (t == 0) {
        unsigned r = atomicAdd(&g_ticket, 1u);
        s_last = (r == (unsigned)nblocks - 1) ? 1 : 0;
    }
    __syncthreads();
    if (s_last) {
        for (int j = t; j < NJ; j += THREADS) {
            float v  = __ldcg(&g_splacc[j]);
            float hi = __ldg(&grid[(size_t)j * NKNOTS + NKNOTS - 1]);
            float lo = __ldg(&grid[(size_t)j * NKNOTS]);
            reg_out[j] = v * inv_batch / (hi - lo + 1e-5f);
            g_splacc[j] = 0.0f;                  // reset for next replay
        }
        __threadfence();
        __syncthreads();
        if (t == 0) atomicExch(&g_ticket, 0u);
    }
}

extern "C" void kernel_launch(void* const* d_in, const int* in_sizes, int n_in,
                              void* d_out, int out_size)
{
    const float* x       = (const float*)d_in[0];
    const float* c_basis = (const float*)d_in[1];
    const float* c_spl   = (const float*)d_in[2];
    const float* c_res   = (const float*)d_in[3];
    const float* grid    = (const float*)d_in[4];

    int batch = in_sizes[0] / NIN;

    float* y_out   = (float*)d_out;                 // (batch, 64)
    float* reg_out = y_out + (size_t)batch * NOUT;  // (64, 64)

    cudaFuncSetAttribute(kan_fused_kernel,
                         cudaFuncAttributeMaxDynamicSharedMemorySize, SMEM_TOTAL);

    int nblocks = (batch + BATCH_TILE - 1) / BATCH_TILE;
    kan_fused_kernel<<<nblocks, THREADS, SMEM_TOTAL>>>(x, c_basis, c_spl, c_res, grid,
                                                       y_out, reg_out, batch,
                                                       1.0f / (float)batch, nblocks);
}

// round 16
// speedup vs baseline: 1.0946x; 1.0946x over previous
#include <cuda_runtime.h>

#define NIN     64
#define NOUT    64
#define NJ      (NIN * NOUT)       // 4096
#define NKNOTS  10
#define NBASIS  6
#define NRCP    24
#define BATCH_TILE 14
#define THREADS 512
#define MAXBLK  160

// ---- dynamic shared layout (bytes) ----
#define SFEAT_OFF   0
#define SFEAT_BYTES (7 * BATCH_TILE * NIN * 4)      // 25088 [c][bl][i]
#define SGRID_OFF   (SFEAT_OFF + SFEAT_BYTES)
#define SGRID_BYTES (NKNOTS * 32 * 8)               // 2560 packed (-kn,-kn')
#define SRCP_OFF    (SGRID_OFF + SGRID_BYTES)
#define SRCP_BYTES  (NRCP * 32 * 8)                 // 6144 packed (+r,+r')
#define SNRCP_OFF   (SRCP_OFF + SRCP_BYTES)
#define SNRCP_BYTES (NRCP * 32 * 8)                 // 6144 packed (-r,-r')
#define SYPART_OFF  (SNRCP_OFF + SNRCP_BYTES)
#define SYPART_BYTES (BATCH_TILE * 16 * 32 * 16)    // 114688 [bl][oq][lane]
#define SMEM_TOTAL  (SYPART_OFF + SYPART_BYTES)     // 154624

typedef unsigned long long ull;
__device__ __forceinline__ ull pack2(float lo, float hi) {
    ull r; asm("mov.b64 %0, {%1, %2};" : "=l"(r) : "f"(lo), "f"(hi)); return r;
}
#define FMA2(d,a,b,c) asm("fma.rn.f32x2 %0, %1, %2, %3;" : "=l"(d) : "l"(a), "l"(b), "l"(c))
#define MUL2(d,a,b)   asm("mul.rn.f32x2 %0, %1, %2;"     : "=l"(d) : "l"(a), "l"(b))
#define ADD2(d,a,b)   asm("add.rn.f32x2 %0, %1, %2;"     : "=l"(d) : "l"(a), "l"(b))
#define UNPK(lo,hi,p) asm("mov.b64 {%0, %1}, %2;" : "=f"(lo), "=f"(hi) : "l"(p))
#define ABSMASK 0x7FFFFFFF7FFFFFFFULL
#define NEG1X2  0xBF800000BF800000ULL

// Per-block |spl| partial sums. Fully overwritten every launch by plain
// stores (no atomics, no reset needed) -> graph-replay safe, deterministic.
__device__ __align__(16) float g_partial[MAXBLK * NJ];

struct Smem {
    float  (*sfeat)[BATCH_TILE][NIN];   // [c][bl][i]
    ull    (*sgridn01)[32];             // [m][ip]  (-kn_i, -kn_{i+1})
    ull    (*srcp01)[32];               // [e][ip]  (+r_i, +r_{i+1})
    ull    (*snrcp01)[32];              // [e][ip]  (-r_i, -r_{i+1})
    float4 (*sypart)[16][32];           // [bl][oq][lane]
};

template <bool FULL>
__device__ __forceinline__
void phase2(const Smem& S, int nbl, int lane, int oq,
            const ull cb01[4][NBASIS], const ull csp01[4],
            const ull crs01[4], ull acc01[4])
{
    #pragma unroll
    for (int bl = 0; bl < BATCH_TILE; bl++) {
        if (!FULL && bl >= nbl) break;
        ull f01[7];
        #pragma unroll
        for (int c = 0; c < 7; c++)
            f01[c] = *(const ull*)&S.sfeat[c][bl][lane * 2];

        float4 yp;
        float* ypp = (float*)&yp;
        #pragma unroll
        for (int q = 0; q < 4; q++) {
            ull s01;
            MUL2(s01, cb01[q][0], f01[0]);
            #pragma unroll
            for (int c = 1; c < NBASIS; c++)
                FMA2(s01, cb01[q][c], f01[c], s01);
            ull a01 = s01 & ABSMASK;             // packed |.|
            ADD2(acc01[q], acc01[q], a01);
            ull t01;
            MUL2(t01, csp01[q], s01);
            FMA2(t01, crs01[q], f01[6], t01);
            float t0, t1; UNPK(t0, t1, t01);
            ypp[q] = t0 + t1;
        }
        S.sypart[bl][oq][lane] = yp;    // fire-and-forget
    }
}

__global__ __launch_bounds__(THREADS, 1)
void kan_main_kernel(const float* __restrict__ x,
                     const float* __restrict__ c_basis,
                     const float* __restrict__ c_spl,
                     const float* __restrict__ c_res,
                     const float* __restrict__ grid,
                     float* __restrict__ y_out,
                     int batch)
{
    extern __shared__ __align__(16) char smem_raw[];
    Smem S;
    S.sfeat    = (float  (*)[BATCH_TILE][NIN])(smem_raw + SFEAT_OFF);
    S.sgridn01 = (ull    (*)[32])(smem_raw + SGRID_OFF);
    S.srcp01   = (ull    (*)[32])(smem_raw + SRCP_OFF);
    S.snrcp01  = (ull    (*)[32])(smem_raw + SNRCP_OFF);
    S.sypart   = (float4 (*)[16][32])(smem_raw + SYPART_OFF);

    const int t    = threadIdx.x;
    const int lane = t & 31;
    const int oq   = t >> 5;
    const int b0   = blockIdx.x * BATCH_TILE;
    const int nbl  = min(BATCH_TILE, batch - b0);

    // ---- phase 0: packed (negated) knots + sign-folded reciprocal tables ----
    for (int p = t; p < NKNOTS * 32; p += THREADS) {
        int ip = p & 31, m = p >> 5;
        int i0 = ip * 2;
        S.sgridn01[m][ip] = pack2(-__ldg(&grid[i0 * NKNOTS + m]),
                                  -__ldg(&grid[(i0 + 1) * NKNOTS + m]));
    }
    for (int p = t; p < NRCP * 32; p += THREADS) {
        int ip = p & 31, e = p >> 5;
        int K = (e < 9) ? 1 : (e < 17) ? 2 : 3;
        int m = (e < 9) ? e : (e < 17) ? e - 9 : e - 17;
        int i0 = ip * 2;
        float r0 = 1.0f / (__ldg(&grid[i0 * NKNOTS + m + K]) - __ldg(&grid[i0 * NKNOTS + m]));
        float r1 = 1.0f / (__ldg(&grid[(i0 + 1) * NKNOTS + m + K]) - __ldg(&grid[(i0 + 1) * NKNOTS + m]));
        S.srcp01[e][ip]  = pack2(r0, r1);
        S.snrcp01[e][ip] = pack2(-r0, -r1);
    }
    __syncthreads();

    // ---- phase 1: packed basis + silu; thread = (bl, i-pair), 448 active ----
    if (t < BATCH_TILE * 32) {
        const int ip = t & 31;
        const int bl = t >> 5;
        int b = b0 + bl;
        float2 xv = (b < batch) ? *(const float2*)&x[(size_t)b * NIN + ip * 2]
                                : make_float2(0.f, 0.f);
        ull x01 = pack2(xv.x, xv.y);

        ull d01[NKNOTS];
        #pragma unroll
        for (int m = 0; m < NKNOTS; m++) {
            ull nk = S.sgridn01[m][ip];
            ADD2(d01[m], x01, nk);               // x - kn[m]
        }

        // bases init: bs[m] = ge[m] - ge[m+1] (rolling, from d01 signs)
        ull bs01[9];
        {
            const ull neg1 = NEG1X2;
            float dA, dB; UNPK(dA, dB, d01[0]);
            ull gprev = pack2(dA >= 0.f ? 1.f : 0.f, dB >= 0.f ? 1.f : 0.f);
            #pragma unroll
            for (int m = 0; m < 9; m++) {
                UNPK(dA, dB, d01[m + 1]);
                ull gnext = pack2(dA >= 0.f ? 1.f : 0.f, dB >= 0.f ? 1.f : 0.f);
                FMA2(bs01[m], gnext, neg1, gprev);
                gprev = gnext;
            }
        }

        #pragma unroll
        for (int K = 1; K <= 3; K++) {
            const int off = (K == 1) ? 0 : (K == 2) ? 9 : 17;
            #pragma unroll
            for (int m = 0; m <= 8 - K; m++) {
                ull rl = S.srcp01[off + m][ip];
                ull rr = S.snrcp01[off + m + 1][ip];
                ull left, w, wb, nb;
                MUL2(left, d01[m], rl);
                MUL2(w, d01[m + K + 1], rr);
                MUL2(wb, w, bs01[m + 1]);
                FMA2(nb, left, bs01[m], wb);
                bs01[m] = nb;
            }
        }
        #pragma unroll
        for (int c = 0; c < NBASIS; c++)
            *(ull*)&S.sfeat[c][bl][ip * 2] = bs01[c];
        float sA = xv.x / (1.0f + __expf(-xv.x));
        float sB = xv.y / (1.0f + __expf(-xv.y));
        *(ull*)&S.sfeat[6][bl][ip * 2] = pack2(sA, sB);
    }

    // ---- coefficients loaded after phase 1 (keeps phase-1 regs low) ----
    ull cb01[4][NBASIS], csp01[4], crs01[4];
    #pragma unroll
    for (int q = 0; q < 4; q++) {
        int j0 = (oq * 4 + q) * NIN + lane * 2;
        const float4* p4 = (const float4*)(c_basis + (size_t)j0 * NBASIS);
        float4 f0 = __ldg(&p4[0]);
        float4 f1 = __ldg(&p4[1]);
        float4 f2 = __ldg(&p4[2]);
        cb01[q][0] = pack2(f0.x, f1.z);
        cb01[q][1] = pack2(f0.y, f1.w);
        cb01[q][2] = pack2(f0.z, f2.x);
        cb01[q][3] = pack2(f0.w, f2.y);
        cb01[q][4] = pack2(f1.x, f2.z);
        cb01[q][5] = pack2(f1.y, f2.w);
        csp01[q] = *(const ull*)&c_spl[j0];
        crs01[q] = *(const ull*)&c_res[j0];
    }
    __syncthreads();

    // ---- phase 2: packed-FMA spl / y-partial / packed |spl| ----
    ull acc01[4] = {0ull, 0ull, 0ull, 0ull};
    if (nbl == BATCH_TILE) phase2<true >(S, nbl, lane, oq, cb01, csp01, crs01, acc01);
    else                   phase2<false>(S, nbl, lane, oq, cb01, csp01, crs01, acc01);

    // ---- |spl| partials: plain packed STG.64 (coalesced, no contention) ----
    {
        float* row = &g_partial[(size_t)blockIdx.x * NJ];
        #pragma unroll
        for (int q = 0; q < 4; q++) {
            int j = (oq * 4 + q) * NIN + lane * 2;
            *(ull*)&row[j] = acc01[q];
        }
    }
    __syncthreads();

    // ---- one-stage epilogue: 224 threads reduce 32 lanes -> y ----
    if (t < BATCH_TILE * 16) {
        int bl = t >> 4, oqr = t & 15;
        if (bl < nbl) {
            float4 s = make_float4(0.f, 0.f, 0.f, 0.f);
            int rot = t & 31;
            #pragma unroll
            for (int k = 0; k < 32; k++) {
                int ls = (k + rot) & 31;         // stagger
                float4 v = S.sypart[bl][oqr][ls];
                s.x += v.x; s.y += v.y; s.z += v.z; s.w += v.w;
            }
            const float sc = 1.0f / NIN;
            s.x *= sc; s.y *= sc; s.z *= sc; s.w *= sc;
            *(float4*)&y_out[(size_t)(b0 + bl) * NOUT + oqr * 4] = s;
        }
    }
}

// ---- second kernel: reduce per-block partials + scale -> spl_reg ----
__global__ __launch_bounds__(512, 1)
void kan_finalize_kernel(const float* __restrict__ grid,
                         float* __restrict__ reg_out,
                         float inv_batch, int nblocks)
{
    int j = blockIdx.x * blockDim.x + threadIdx.x;
    if (j >= NJ) return;
    float s0 = 0.f, s1 = 0.f, s2 = 0.f, s3 = 0.f;
    const float* p = &g_partial[j];
    int b2 = 0;
    for (; b2 + 4 <= nblocks; b2 += 4) {
        s0 += __ldcg(&p[(size_t)(b2 + 0) * NJ]);
        s1 += __ldcg(&p[(size_t)(b2 + 1) * NJ]);
        s2 += __ldcg(&p[(size_t)(b2 + 2) * NJ]);
        s3 += __ldcg(&p[(size_t)(b2 + 3) * NJ]);
    }
    for (; b2 < nblocks; b2++) s0 += __ldcg(&p[(size_t)b2 * NJ]);
    float s = (s0 + s1) + (s2 + s3);
    float hi = __ldg(&grid[(size_t)j * NKNOTS + NKNOTS - 1]);
    float lo = __ldg(&grid[(size_t)j * NKNOTS]);
    reg_out[j] = s * inv_batch / (hi - lo + 1e-5f);
}

extern "C" void kernel_launch(void* const* d_in, const int* in_sizes, int n_in,
                              void* d_out, int out_size)
{
    const float* x       = (const float*)d_in[0];
    const float* c_basis = (const float*)d_in[1];
    const float* c_spl   = (const float*)d_in[2];
    const float* c_res   = (const float*)d_in[3];
    const float* grid    = (const float*)d_in[4];

    int batch = in_sizes[0] / NIN;

    float* y_out   = (float*)d_out;                 // (batch, 64)
    float* reg_out = y_out + (size_t)batch * NOUT;  // (64, 64)

    cudaFuncSetAttribute(kan_main_kernel,
                         cudaFuncAttributeMaxDynamicSharedMemorySize, SMEM_TOTAL);

    int nblocks = (batch + BATCH_TILE - 1) / BATCH_TILE;   // 147 for batch=2048
    kan_main_kernel<<<nblocks, THREADS, SMEM_TOTAL>>>(x, c_basis, c_spl, c_res,
                                                      grid, y_out, batch);
    kan_finalize_kernel<<<(NJ + 511) / 512, 512>>>(grid, reg_out,
                                                   1.0f / (float)batch, nblocks);
}

// round 17
// speedup vs baseline: 1.2296x; 1.1233x over previous
#include <cuda_runtime.h>

#define NIN     64
#define NOUT    64
#define NJ      (NIN * NOUT)       // 4096
#define NKNOTS  10
#define NBASIS  6
#define NRCP    24
#define BATCH_TILE 14
#define THREADS 512
#define MAXBLK  160

// ---- dynamic shared layout (bytes) ----
#define SFEAT_OFF   0
#define SFEAT_BYTES (7 * BATCH_TILE * NIN * 4)      // 25088 [c][bl][i]
#define SGRID_OFF   (SFEAT_OFF + SFEAT_BYTES)
#define SGRID_BYTES (NKNOTS * 32 * 8)               // 2560 packed (-kn,-kn')
#define SRCP_OFF    (SGRID_OFF + SGRID_BYTES)
#define SRCP_BYTES  (NRCP * 32 * 8)                 // 6144 packed (+r,+r')
#define SNRCP_OFF   (SRCP_OFF + SRCP_BYTES)
#define SNRCP_BYTES (NRCP * 32 * 8)                 // 6144 packed (-r,-r')
#define SYPART_OFF  (SNRCP_OFF + SNRCP_BYTES)
#define SYPART_BYTES (BATCH_TILE * 16 * 32 * 16)    // 114688 [bl][oq][lane]
#define SMEM_TOTAL  (SYPART_OFF + SYPART_BYTES)     // 154624

typedef unsigned long long ull;
__device__ __forceinline__ ull pack2(float lo, float hi) {
    ull r; asm("mov.b64 %0, {%1, %2};" : "=l"(r) : "f"(lo), "f"(hi)); return r;
}
#define FMA2(d,a,b,c) asm("fma.rn.f32x2 %0, %1, %2, %3;" : "=l"(d) : "l"(a), "l"(b), "l"(c))
#define MUL2(d,a,b)   asm("mul.rn.f32x2 %0, %1, %2;"     : "=l"(d) : "l"(a), "l"(b))
#define ADD2(d,a,b)   asm("add.rn.f32x2 %0, %1, %2;"     : "=l"(d) : "l"(a), "l"(b))
#define UNPK(lo,hi,p) asm("mov.b64 {%0, %1}, %2;" : "=f"(lo), "=f"(hi) : "l"(p))
#define ABSMASK 0x7FFFFFFF7FFFFFFFULL
#define NEG1X2  0xBF800000BF800000ULL

// Per-block |spl| partial sums. Fully overwritten every launch by plain
// stores (no atomics, no reset needed) -> graph-replay safe, deterministic.
__device__ __align__(16) float g_partial[MAXBLK * NJ];

struct Smem {
    float  (*sfeat)[BATCH_TILE][NIN];   // [c][bl][i]
    ull    (*sgridn01)[32];             // [m][ip]  (-kn_i, -kn_{i+1})
    ull    (*srcp01)[32];               // [e][ip]  (+r_i, +r_{i+1})
    ull    (*snrcp01)[32];              // [e][ip]  (-r_i, -r_{i+1})
    float4 (*sypart)[16][32];           // [bl][oq][lane]
};

template <bool FULL>
__device__ __forceinline__
void phase2(const Smem& S, int nbl, int lane, int oq,
            const ull cb01[4][NBASIS], const ull csp01[4],
            const ull crs01[4], ull acc01[4])
{
    #pragma unroll
    for (int bl = 0; bl < BATCH_TILE; bl++) {
        if (!FULL && bl >= nbl) break;
        ull f01[7];
        #pragma unroll
        for (int c = 0; c < 7; c++)
            f01[c] = *(const ull*)&S.sfeat[c][bl][lane * 2];

        float4 yp;
        float* ypp = (float*)&yp;
        #pragma unroll
        for (int q = 0; q < 4; q++) {
            ull s01;
            MUL2(s01, cb01[q][0], f01[0]);
            #pragma unroll
            for (int c = 1; c < NBASIS; c++)
                FMA2(s01, cb01[q][c], f01[c], s01);
            ull a01 = s01 & ABSMASK;             // packed |.|
            ADD2(acc01[q], acc01[q], a01);
            ull t01;
            MUL2(t01, csp01[q], s01);
            FMA2(t01, crs01[q], f01[6], t01);
            float t0, t1; UNPK(t0, t1, t01);
            ypp[q] = t0 + t1;
        }
        S.sypart[bl][oq][lane] = yp;    // fire-and-forget
    }
}

__global__ __launch_bounds__(THREADS, 1)
void kan_main_kernel(const float* __restrict__ x,
                     const float* __restrict__ c_basis,
                     const float* __restrict__ c_spl,
                     const float* __restrict__ c_res,
                     const float* __restrict__ grid,
                     float* __restrict__ y_out,
                     int batch)
{
    extern __shared__ __align__(16) char smem_raw[];
    Smem S;
    S.sfeat    = (float  (*)[BATCH_TILE][NIN])(smem_raw + SFEAT_OFF);
    S.sgridn01 = (ull    (*)[32])(smem_raw + SGRID_OFF);
    S.srcp01   = (ull    (*)[32])(smem_raw + SRCP_OFF);
    S.snrcp01  = (ull    (*)[32])(smem_raw + SNRCP_OFF);
    S.sypart   = (float4 (*)[16][32])(smem_raw + SYPART_OFF);

    const int t    = threadIdx.x;
    const int lane = t & 31;
    const int oq   = t >> 5;
    const int b0   = blockIdx.x * BATCH_TILE;
    const int nbl  = min(BATCH_TILE, batch - b0);

    // ---- phase 0: packed (negated) knots + sign-folded reciprocal tables ----
    for (int p = t; p < NKNOTS * 32; p += THREADS) {
        int ip = p & 31, m = p >> 5;
        int i0 = ip * 2;
        S.sgridn01[m][ip] = pack2(-__ldg(&grid[i0 * NKNOTS + m]),
                                  -__ldg(&grid[(i0 + 1) * NKNOTS + m]));
    }
    for (int p = t; p < NRCP * 32; p += THREADS) {
        int ip = p & 31, e = p >> 5;
        int K = (e < 9) ? 1 : (e < 17) ? 2 : 3;
        int m = (e < 9) ? e : (e < 17) ? e - 9 : e - 17;
        int i0 = ip * 2;
        float r0 = 1.0f / (__ldg(&grid[i0 * NKNOTS + m + K]) - __ldg(&grid[i0 * NKNOTS + m]));
        float r1 = 1.0f / (__ldg(&grid[(i0 + 1) * NKNOTS + m + K]) - __ldg(&grid[(i0 + 1) * NKNOTS + m]));
        S.srcp01[e][ip]  = pack2(r0, r1);
        S.snrcp01[e][ip] = pack2(-r0, -r1);
    }
    __syncthreads();

    // ---- phase 1: packed basis + silu; thread = (bl, i-pair), 448 active ----
    if (t < BATCH_TILE * 32) {
        const int ip = t & 31;
        const int bl = t >> 5;
        int b = b0 + bl;
        float2 xv = (b < batch) ? *(const float2*)&x[(size_t)b * NIN + ip * 2]
                                : make_float2(0.f, 0.f);
        ull x01 = pack2(xv.x, xv.y);

        ull d01[NKNOTS];
        #pragma unroll
        for (int m = 0; m < NKNOTS; m++) {
            ull nk = S.sgridn01[m][ip];
            ADD2(d01[m], x01, nk);               // x - kn[m]
        }

        // bases init: bs[m] = ge[m] - ge[m+1] (rolling, from d01 signs)
        ull bs01[9];
        {
            const ull neg1 = NEG1X2;
            float dA, dB; UNPK(dA, dB, d01[0]);
            ull gprev = pack2(dA >= 0.f ? 1.f : 0.f, dB >= 0.f ? 1.f : 0.f);
            #pragma unroll
            for (int m = 0; m < 9; m++) {
                UNPK(dA, dB, d01[m + 1]);
                ull gnext = pack2(dA >= 0.f ? 1.f : 0.f, dB >= 0.f ? 1.f : 0.f);
                FMA2(bs01[m], gnext, neg1, gprev);
                gprev = gnext;
            }
        }

        #pragma unroll
        for (int K = 1; K <= 3; K++) {
            const int off = (K == 1) ? 0 : (K == 2) ? 9 : 17;
            #pragma unroll
            for (int m = 0; m <= 8 - K; m++) {
                ull rl = S.srcp01[off + m][ip];
                ull rr = S.snrcp01[off + m + 1][ip];
                ull left, w, wb, nb;
                MUL2(left, d01[m], rl);
                MUL2(w, d01[m + K + 1], rr);
                MUL2(wb, w, bs01[m + 1]);
                FMA2(nb, left, bs01[m], wb);
                bs01[m] = nb;
            }
        }
        #pragma unroll
        for (int c = 0; c < NBASIS; c++)
            *(ull*)&S.sfeat[c][bl][ip * 2] = bs01[c];
        float sA = xv.x / (1.0f + __expf(-xv.x));
        float sB = xv.y / (1.0f + __expf(-xv.y));
        *(ull*)&S.sfeat[6][bl][ip * 2] = pack2(sA, sB);
    }

    // ---- coefficients loaded after phase 1 (keeps phase-1 regs low) ----
    ull cb01[4][NBASIS], csp01[4], crs01[4];
    #pragma unroll
    for (int q = 0; q < 4; q++) {
        int j0 = (oq * 4 + q) * NIN + lane * 2;
        const float4* p4 = (const float4*)(c_basis + (size_t)j0 * NBASIS);
        float4 f0 = __ldg(&p4[0]);
        float4 f1 = __ldg(&p4[1]);
        float4 f2 = __ldg(&p4[2]);
        cb01[q][0] = pack2(f0.x, f1.z);
        cb01[q][1] = pack2(f0.y, f1.w);
        cb01[q][2] = pack2(f0.z, f2.x);
        cb01[q][3] = pack2(f0.w, f2.y);
        cb01[q][4] = pack2(f1.x, f2.z);
        cb01[q][5] = pack2(f1.y, f2.w);
        csp01[q] = *(const ull*)&c_spl[j0];
        crs01[q] = *(const ull*)&c_res[j0];
    }
    __syncthreads();

    // ---- phase 2: packed-FMA spl / y-partial / packed |spl| ----
    ull acc01[4] = {0ull, 0ull, 0ull, 0ull};
    if (nbl == BATCH_TILE) phase2<true >(S, nbl, lane, oq, cb01, csp01, crs01, acc01);
    else                   phase2<false>(S, nbl, lane, oq, cb01, csp01, crs01, acc01);

    // ---- |spl| partials: plain packed STG.64 (coalesced, no contention) ----
    {
        float* row = &g_partial[(size_t)blockIdx.x * NJ];
        #pragma unroll
        for (int q = 0; q < 4; q++) {
            int j = (oq * 4 + q) * NIN + lane * 2;
            *(ull*)&row[j] = acc01[q];
        }
    }
    __syncthreads();

    // ---- one-stage epilogue: 224 threads reduce 32 lanes -> y ----
    if (t < BATCH_TILE * 16) {
        int bl = t >> 4, oqr = t & 15;
        if (bl < nbl) {
            float4 s = make_float4(0.f, 0.f, 0.f, 0.f);
            int rot = t & 31;
            #pragma unroll
            for (int k = 0; k < 32; k++) {
                int ls = (k + rot) & 31;         // stagger
                float4 v = S.sypart[bl][oqr][ls];
                s.x += v.x; s.y += v.y; s.z += v.z; s.w += v.w;
            }
            const float sc = 1.0f / NIN;
            s.x *= sc; s.y *= sc; s.z *= sc; s.w *= sc;
            *(float4*)&y_out[(size_t)(b0 + bl) * NOUT + oqr * 4] = s;
        }
    }
}

// ---- finalize v2: parallel partial reduction -> spl_reg ----
// 128 blocks x 512 threads; block owns 32 consecutive j.
// thread = (jloc 0..31, slice 0..15); each thread sums ~10 partials
// (independent loads, full MLP, coalesced across jloc), shared 16-way
// combine, 32 threads write with norm folded in.
__global__ __launch_bounds__(512, 1)
void kan_finalize_kernel(const float* __restrict__ grid,
                         float* __restrict__ reg_out,
                         float inv_batch, int nblocks)
{
    __shared__ float red[16][33];     // [slice][jloc] (+1 pad)
    const int t     = threadIdx.x;
    const int jloc  = t & 31;
    const int slice = t >> 5;         // 0..15
    const int j     = blockIdx.x * 32 + jloc;

    float s = 0.f;
    for (int b = slice; b < nblocks; b += 16)
        s += __ldcg(&g_partial[(size_t)b * NJ + j]);
    red[slice][jloc] = s;
    __syncthreads();

    if (t < 32) {
        float acc = 0.f;
        #pragma unroll
        for (int k = 0; k < 16; k++) acc += red[k][t];
        int jj = blockIdx.x * 32 + t;
        float hi = __ldg(&grid[(size_t)jj * NKNOTS + NKNOTS - 1]);
        float lo = __ldg(&grid[(size_t)jj * NKNOTS]);
        reg_out[jj] = acc * inv_batch / (hi - lo + 1e-5f);
    }
}

extern "C" void kernel_launch(void* const* d_in, const int* in_sizes, int n_in,
                              void* d_out, int out_size)
{
    const float* x       = (const float*)d_in[0];
    const float* c_basis = (const float*)d_in[1];
    const float* c_spl   = (const float*)d_in[2];
    const float* c_res   = (const float*)d_in[3];
    const float* grid    = (const float*)d_in[4];

    int batch = in_sizes[0] / NIN;

    float* y_out   = (float*)d_out;                 // (batch, 64)
    float* reg_out = y_out + (size_t)batch * NOUT;  // (64, 64)

    cudaFuncSetAttribute(kan_main_kernel,
                         cudaFuncAttributeMaxDynamicSharedMemorySize, SMEM_TOTAL);

    int nblocks = (batch + BATCH_TILE - 1) / BATCH_TILE;   // 147 for batch=2048
    kan_main_kernel<<<nblocks, THREADS, SMEM_TOTAL>>>(x, c_basis, c_spl, c_res,
                                                      grid, y_out, batch);
    kan_finalize_kernel<<<NJ / 32, 512>>>(grid, reg_out,
                                          1.0f / (float)batch, nblocks);
}